// round 4
// baseline (speedup 1.0000x reference)
#include <cuda_runtime.h>
#include <math.h>

// Problem constants: x is (64, 128, 10000) fp32.
#define BATCH 64
#define CH    128
#define T_LEN 10000
#define TT    64           // time-tile per stats block
#define PITCH 65           // odd pitch -> conflict-free row & column smem access
#define T4    (T_LEN / 4)  // 2500

// Scratch (no allocations allowed). Statically zero-initialized.
__device__ float g_m[BATCH * T_LEN];      // mean over channels at each (b,t)
__device__ float g_sum [BATCH * CH];      // sum of y over time (accumulator)
__device__ float g_sum2[BATCH * CH];      // sum of y^2 over time (accumulator)
__device__ float g_mean[BATCH * CH];
__device__ float g_istd[BATCH * CH];

// ---------------------------------------------------------------- kernel 1: tiled stats
// Block = (b, t-chunk of TT), 256 threads = 8 warps, ~34.6 KB smem -> 6 blocks/SM.
// Thread group g = tid>>6 (0..3) covers channels [g*32, g*32+32) at time tx = tid&63.
// Streams x into smem tile while register-accumulating the per-t channel partial sum.
__global__ __launch_bounds__(256) void eeg_stats_kernel(const float* __restrict__ x) {
    extern __shared__ float s[];
    float* tile = s;                       // CH * PITCH      (8320 floats)
    float* mrow = s + CH * PITCH;          // TT              (channel mean per t)
    float* part = mrow + TT;               // 4 * TT          (per-group colsum partials)

    const int b    = blockIdx.y;
    const int t0   = blockIdx.x * TT;
    const int tid  = threadIdx.x;
    const int tx   = tid & (TT - 1);       // 0..63 time within tile
    const int g    = tid >> 6;             // 0..3 channel group
    const int vlen = min(TT, T_LEN - t0);
    const bool valid = tx < vlen;

    const float* __restrict__ xp =
        x + (size_t)b * CH * T_LEN + (size_t)(g * 32) * T_LEN + t0 + tx;
    float* tp = tile + (g * 32) * PITCH + tx;

    // Phase 1: stream 32 channel rows; store tile + register colsum.
    float csum = 0.f;
    #pragma unroll 8
    for (int c = 0; c < 32; ++c) {
        float v = valid ? __ldg(xp + (size_t)c * T_LEN) : 0.f;
        tp[c * PITCH] = v;
        csum += v;
    }
    part[g * TT + tx] = csum;
    __syncthreads();

    // Combine 4 group partials -> channel mean m[t]; write g_m. (first 64 threads)
    if (tid < TT) {
        float m = (part[tid] + part[TT + tid] + part[2 * TT + tid] + part[3 * TT + tid])
                  * (1.0f / 128.0f);
        mrow[tid] = m;
        if (tid < vlen) g_m[(size_t)b * T_LEN + t0 + tid] = m;
    }
    __syncthreads();

    // Phase 2: per-channel accumulation of y = x - m and y^2 over this t-chunk.
    // Thread (c = tid&127, h = tid>>7) covers 32 time steps.
    {
        const int c  = tid & (CH - 1);
        const int h  = tid >> 7;
        const int tb = h * 32;
        const int te = min(tb + 32, vlen);
        float sy = 0.f, sy2 = 0.f;
        const float* trow = tile + c * PITCH;
        #pragma unroll 8
        for (int t = tb; t < te; ++t) {
            float v = trow[t] - mrow[t];       // mrow[t]: broadcast read
            sy  += v;
            sy2 += v * v;
        }
        if (te > tb) {
            atomicAdd(&g_sum [b * CH + c], sy);
            atomicAdd(&g_sum2[b * CH + c], sy2);
        }
    }
}

// ---------------------------------------------------------------- kernel 2: finalize + re-zero
// Consumes the accumulators and resets them to zero so the next graph replay
// starts from a clean state (they are statically zero-initialized).
__global__ void eeg_finalize_kernel() {
    int i = blockIdx.x * blockDim.x + threadIdx.x;
    if (i < BATCH * CH) {
        const float inv_t = 1.0f / (float)T_LEN;
        float mean = g_sum[i] * inv_t;
        float var  = g_sum2[i] * inv_t - mean * mean;
        float sd   = sqrtf(fmaxf(var, 0.f));
        g_mean[i] = mean;
        g_istd[i] = (sd == 0.f) ? 1.f : (1.f / sd);
        g_sum [i] = 0.f;
        g_sum2[i] = 0.f;
    }
}

// ---------------------------------------------------------------- kernel 3: normalize
// grid = (5, 8192): blockIdx.y = (b,c) pair. 2 float4 per thread, loads front-batched.
__global__ __launch_bounds__(256) void eeg_norm_kernel(const float4* __restrict__ x4,
                                                       float4* __restrict__ o4) {
    const int bc = blockIdx.y;
    const int b  = bc >> 7;
    const int ta = blockIdx.x * 512 + threadIdx.x;
    const int tb = ta + 256;

    const float mean = g_mean[bc];
    const float istd = g_istd[bc];

    const float4* __restrict__ xp = x4 + (size_t)bc * T4;
    float4*                   op = o4 + (size_t)bc * T4;
    const float4* __restrict__ mp =
        reinterpret_cast<const float4*>(g_m + (size_t)b * T_LEN);

    const bool va = ta < T4;
    const bool vb = tb < T4;

    float4 v0, v1, m0, m1;
    if (va) { v0 = xp[ta]; m0 = mp[ta]; }
    if (vb) { v1 = xp[tb]; m1 = mp[tb]; }

    if (va) {
        float4 r;
        r.x = (v0.x - m0.x - mean) * istd;
        r.y = (v0.y - m0.y - mean) * istd;
        r.z = (v0.z - m0.z - mean) * istd;
        r.w = (v0.w - m0.w - mean) * istd;
        op[ta] = r;
    }
    if (vb) {
        float4 r;
        r.x = (v1.x - m1.x - mean) * istd;
        r.y = (v1.y - m1.y - mean) * istd;
        r.z = (v1.z - m1.z - mean) * istd;
        r.w = (v1.w - m1.w - mean) * istd;
        op[tb] = r;
    }
}

// ---------------------------------------------------------------- launch
extern "C" void kernel_launch(void* const* d_in, const int* in_sizes, int n_in,
                              void* d_out, int out_size) {
    (void)in_sizes; (void)n_in; (void)out_size;
    const float* x = (const float*)d_in[0];
    float* out = (float*)d_out;

    static const size_t smem_bytes = (CH * PITCH + 5 * TT) * sizeof(float);  // ~34.6 KB
    cudaFuncSetAttribute(eeg_stats_kernel,
                         cudaFuncAttributeMaxDynamicSharedMemorySize,
                         (int)smem_bytes);

    // 1) tiled stats (accumulators start zeroed; finalize re-zeroes them)
    dim3 sgrid((T_LEN + TT - 1) / TT, BATCH);    // (157, 64)
    eeg_stats_kernel<<<sgrid, 256, smem_bytes>>>(x);

    // 2) finalize mean / inv_std + reset accumulators
    eeg_finalize_kernel<<<(BATCH * CH + 255) / 256, 256>>>();

    // 3) normalize
    dim3 ngrid((T4 + 511) / 512, BATCH * CH);    // (5, 8192)
    eeg_norm_kernel<<<ngrid, 256>>>((const float4*)x, (float4*)out);
}

// round 5
// speedup vs baseline: 1.1380x; 1.1380x over previous
#include <cuda_runtime.h>
#include <math.h>

// Problem constants: x is (64, 128, 10000) fp32.
#define BATCH 64
#define CH    128
#define T_LEN 10000
#define TT    128          // time-tile per stats block
#define PITCH 132          // stride ≡ 4 (mod 32) -> conflict-free LDS.128 column reads
#define T4    (T_LEN / 4)  // 2500

// Scratch (no allocations allowed). Statically zero-initialized.
__device__ float g_m[BATCH * T_LEN];      // mean over channels at each (b,t)
__device__ float g_sum [BATCH * CH];      // sum of y over time (accumulator)
__device__ float g_sum2[BATCH * CH];      // sum of y^2 over time (accumulator)
__device__ float g_mean[BATCH * CH];
__device__ float g_istd[BATCH * CH];

// ---------------------------------------------------------------- kernel 1: tiled stats
// Block = (b, t-chunk of TT=128), 256 threads = 8 warps, ~72 KB smem -> 3 blocks/SM.
// Phase 1: warp w loads channels [w*16, w*16+16); lane l owns the float4 at t=4l.
//          One LDG.128 + one STS.128 per channel row; float4 register colsum.
// Phase 2: per-channel sums read back via conflict-free LDS.128 (PITCH=132).
__global__ __launch_bounds__(256) void eeg_stats_kernel(const float* __restrict__ x) {
    extern __shared__ float s[];
    float* tile = s;                       // CH * PITCH floats  (67584 B)
    float* mrow = s + CH * PITCH;          // TT                 (channel mean per t)
    float* part = mrow + TT;               // 8 * TT             (per-warp colsum partials)

    const int b    = blockIdx.y;
    const int t0   = blockIdx.x * TT;
    const int tid  = threadIdx.x;
    const int lane = tid & 31;
    const int w    = tid >> 5;             // warp 0..7
    const int t    = 4 * lane;             // float4 position within tile
    const int vlen = min(TT, T_LEN - t0);  // 128 or 16 (tail); always multiple of 4
    const bool valid = t < vlen;
    const int cbase = w * 16;

    const float* __restrict__ xp =
        x + (size_t)b * CH * T_LEN + (size_t)cbase * T_LEN + t0 + t;

    // Phase 1: stream 16 channel rows per warp; store tile + float4 register colsum.
    float4 csum = make_float4(0.f, 0.f, 0.f, 0.f);
    #pragma unroll 4
    for (int c = 0; c < 16; ++c) {
        float4 v = valid ? *reinterpret_cast<const float4*>(xp + (size_t)c * T_LEN)
                         : make_float4(0.f, 0.f, 0.f, 0.f);
        *reinterpret_cast<float4*>(&tile[(cbase + c) * PITCH + t]) = v;
        csum.x += v.x; csum.y += v.y; csum.z += v.z; csum.w += v.w;
    }
    *reinterpret_cast<float4*>(&part[w * TT + t]) = csum;
    __syncthreads();

    // Combine 8 warp partials -> channel mean m[t]; write g_m. (first 128 threads)
    if (tid < TT) {
        float m = 0.f;
        #pragma unroll
        for (int w2 = 0; w2 < 8; ++w2) m += part[w2 * TT + tid];
        m *= (1.0f / 128.0f);
        mrow[tid] = m;
        if (tid < vlen) g_m[(size_t)b * T_LEN + t0 + tid] = m;
    }
    __syncthreads();

    // Phase 2: per-channel accumulation of y = x - m and y^2 over this t-chunk.
    // Thread (c = tid&127, h = tid>>7) covers t in [h*64, h*64+64) via float4.
    {
        const int c  = tid & (CH - 1);
        const int h  = tid >> 7;
        const int tb = h * 64;
        const int te = min(tb + 64, vlen);
        float sy = 0.f, sy2 = 0.f;
        const float* trow = tile + c * PITCH;
        #pragma unroll 4
        for (int tt = tb; tt < te; tt += 4) {
            float4 v  = *reinterpret_cast<const float4*>(&trow[tt]);
            float4 m4 = *reinterpret_cast<const float4*>(&mrow[tt]);   // broadcast
            float a0 = v.x - m4.x, a1 = v.y - m4.y, a2 = v.z - m4.z, a3 = v.w - m4.w;
            sy  += (a0 + a1) + (a2 + a3);
            sy2 += a0 * a0 + a1 * a1 + a2 * a2 + a3 * a3;
        }
        if (te > tb) {
            atomicAdd(&g_sum [b * CH + c], sy);
            atomicAdd(&g_sum2[b * CH + c], sy2);
        }
    }
}

// ---------------------------------------------------------------- kernel 2: finalize + re-zero
__global__ void eeg_finalize_kernel() {
    int i = blockIdx.x * blockDim.x + threadIdx.x;
    if (i < BATCH * CH) {
        const float inv_t = 1.0f / (float)T_LEN;
        float mean = g_sum[i] * inv_t;
        float var  = g_sum2[i] * inv_t - mean * mean;
        float sd   = sqrtf(fmaxf(var, 0.f));
        g_mean[i] = mean;
        g_istd[i] = (sd == 0.f) ? 1.f : (1.f / sd);
        g_sum [i] = 0.f;       // reset for next graph replay (statically zero-init)
        g_sum2[i] = 0.f;
    }
}

// ---------------------------------------------------------------- kernel 3: normalize
// grid = (5, 8192): blockIdx.y = (b,c) pair. 2 float4 per thread, loads front-batched.
__global__ __launch_bounds__(256) void eeg_norm_kernel(const float4* __restrict__ x4,
                                                       float4* __restrict__ o4) {
    const int bc = blockIdx.y;
    const int b  = bc >> 7;
    const int ta = blockIdx.x * 512 + threadIdx.x;
    const int tb = ta + 256;

    const float mean = g_mean[bc];
    const float istd = g_istd[bc];

    const float4* __restrict__ xp = x4 + (size_t)bc * T4;
    float4*                   op = o4 + (size_t)bc * T4;
    const float4* __restrict__ mp =
        reinterpret_cast<const float4*>(g_m + (size_t)b * T_LEN);

    const bool va = ta < T4;
    const bool vb = tb < T4;

    float4 v0, v1, m0, m1;
    if (va) { v0 = xp[ta]; m0 = mp[ta]; }
    if (vb) { v1 = xp[tb]; m1 = mp[tb]; }

    if (va) {
        float4 r;
        r.x = (v0.x - m0.x - mean) * istd;
        r.y = (v0.y - m0.y - mean) * istd;
        r.z = (v0.z - m0.z - mean) * istd;
        r.w = (v0.w - m0.w - mean) * istd;
        op[ta] = r;
    }
    if (vb) {
        float4 r;
        r.x = (v1.x - m1.x - mean) * istd;
        r.y = (v1.y - m1.y - mean) * istd;
        r.z = (v1.z - m1.z - mean) * istd;
        r.w = (v1.w - m1.w - mean) * istd;
        op[tb] = r;
    }
}

// ---------------------------------------------------------------- launch
extern "C" void kernel_launch(void* const* d_in, const int* in_sizes, int n_in,
                              void* d_out, int out_size) {
    (void)in_sizes; (void)n_in; (void)out_size;
    const float* x = (const float*)d_in[0];
    float* out = (float*)d_out;

    static const size_t smem_bytes = (CH * PITCH + 9 * TT) * sizeof(float);  // ~72 KB
    cudaFuncSetAttribute(eeg_stats_kernel,
                         cudaFuncAttributeMaxDynamicSharedMemorySize,
                         (int)smem_bytes);

    // 1) tiled stats (accumulators start zeroed; finalize re-zeroes them)
    dim3 sgrid((T_LEN + TT - 1) / TT, BATCH);    // (79, 64)
    eeg_stats_kernel<<<sgrid, 256, smem_bytes>>>(x);

    // 2) finalize mean / inv_std + reset accumulators
    eeg_finalize_kernel<<<(BATCH * CH + 255) / 256, 256>>>();

    // 3) normalize
    dim3 ngrid((T4 + 511) / 512, BATCH * CH);    // (5, 8192)
    eeg_norm_kernel<<<ngrid, 256>>>((const float4*)x, (float4*)out);
}